// round 9
// baseline (speedup 1.0000x reference)
#include <cuda_runtime.h>

#define NN 8192
#define DD 128
#define CC 100
#define HBLK 64          // label chunks of 128 rows
#define GRID 148         // <= SM count -> all CTAs co-resident at occ 1
#define TI 96
#define THREADS 512
#define MAXT 7400
#define SMEM_DYN ((2 * TI + TI) * DD * 4)   // At2 (dup, 96KB) + Bt (48KB) = 144KB

typedef unsigned long long ull;

// ---------------- device scratch (zero-init; counters self-reset) --------
__device__ int    g_counts[HBLK][CC];
__device__ int    g_classOff[CC + 1];
__device__ int    g_blockOff[HBLK][CC];
__device__ int    g_perm[NN];
__device__ int    g_taskC[MAXT], g_taskI[MAXT], g_taskJ[MAXT];
__device__ int    g_ntasks;
__device__ double g_tileRes[MAXT];
__device__ double g_partialS[GRID];
__device__ float  g_partialM[GRID][DD];
__device__ unsigned g_barCnt;
__device__ int    g_ticket;

__device__ __forceinline__ float f2lo(ull v) { return __uint_as_float((unsigned)v); }
__device__ __forceinline__ float f2hi(ull v) { return __uint_as_float((unsigned)(v >> 32)); }

__device__ __forceinline__ void grid_barrier(unsigned target) {
    __syncthreads();
    if (threadIdx.x == 0) {
        __threadfence();
        atomicAdd(&g_barCnt, 1u);
        while (atomicAdd(&g_barCnt, 0u) < target) { }
        __threadfence();
    }
    __syncthreads();
}

// int64 labels in [0,100) stored LE look like [v,0,v,0,...] as int32 words.
__device__ __forceinline__ int detect_mode(const int* y32, int t, int nthr) {
    __shared__ int s_mode;
    if (t == 0) s_mode = 1;
    __syncthreads();
    int bad = 0;
    for (int i = t; i < NN / 2; i += nthr)
        if (y32[2 * i + 1] != 0) bad = 1;
    if (bad) atomicExch(&s_mode, 0);
    __syncthreads();
    return s_mode;                 // 1 = int64, 0 = int32
}

__global__ void __launch_bounds__(THREADS, 1) k_main(const float* __restrict__ x,
                                                     const int* __restrict__ y32,
                                                     float* __restrict__ out) {
    extern __shared__ float dyn[];
    float* At2 = dyn;                    // [DD][2*TI], each value duplicated {v,v}
    float* Bt  = dyn + DD * 2 * TI;      // [DD][TI] k-major
    __shared__ float  sqP[2 * TI][2];    // per-row half-norm partials (A rows 0..95, B rows 96..191)
    __shared__ float  s_sq[2 * TI];      // folded norms
    __shared__ double red[THREADS];
    __shared__ float  s_sm[THREADS], s_ss[THREADS];
    __shared__ int    s_h[CC];
    __shared__ int    s_lab[128];
    __shared__ int    s_tot[CC];
    __shared__ int    s_isLast;

    const int t = threadIdx.x;
    const int bid = blockIdx.x;
    const int tx = t & 15, ty = t >> 4;   // ty 0..31
    const int i0 = ty * 3, j0 = tx * 6;

    // =========== Phase A: stats slice + (blocks 0..63) label histogram ====
    {
        int c = t & 127, h = t >> 7;      // 4-way row split
        float m = 0.f, s = 0.f;
        #pragma unroll 4
        for (int w = h; bid + GRID * w < NN; w += 4) {
            float v = x[(bid + GRID * w) * DD + c];
            m += v; s += v * v;
        }
        s_sm[t] = m; s_ss[t] = s;
        __syncthreads();
        if (t < 128) g_partialM[bid][t] = s_sm[t] + s_sm[t + 128] + s_sm[t + 256] + s_sm[t + 384];
        for (int s2 = 256; s2 > 0; s2 >>= 1) {
            if (t < s2) s_ss[t] += s_ss[t + s2];
            __syncthreads();
        }
        if (t == 0) g_partialS[bid] = (double)s_ss[0];
    }
    int mode = 1;
    if (bid < HBLK) {
        mode = detect_mode(y32, t, THREADS);
        if (t < CC) s_h[t] = 0;
        __syncthreads();
        if (t < 128) {
            int i = bid * 128 + t;
            int c = mode ? y32[2 * i] : y32[i];
            atomicAdd(&s_h[c], 1);
        }
        __syncthreads();
        if (t < CC) g_counts[bid][t] = s_h[t];
    }
    grid_barrier(GRID);

    // =========== Phase B: block 0 builds offsets + flat tile-task list ====
    if (bid == 0) {
        if (t < CC) {
            int run = 0;
            for (int b = 0; b < HBLK; b++) { g_blockOff[b][t] = run; run += g_counts[b][t]; }
            s_tot[t] = run;
        }
        __syncthreads();
        if (t == 0) {
            int run = 0;
            for (int c = 0; c < CC; c++) { g_classOff[c] = run; run += s_tot[c]; }
            g_classOff[CC] = run;
            int nt = 0;
            for (int c = 0; c < CC; c++) {
                int m2 = (s_tot[c] + TI - 1) / TI;
                for (int a = 0; a < m2 && nt < MAXT; a++)
                    for (int b = 0; b < m2 && nt < MAXT; b++) {
                        g_taskC[nt] = c; g_taskI[nt] = a * TI; g_taskJ[nt] = b * TI; nt++;
                    }
            }
            g_ntasks = nt;
        }
    }
    grid_barrier(2 * GRID);

    // =========== Phase C: blocks 0..63 stable scatter (parallel rank) =====
    if (bid < HBLK) {
        if (t < 128) {
            int base = bid * 128;
            int c = mode ? y32[2 * (base + t)] : y32[base + t];
            s_lab[t] = c;
        }
        __syncthreads();
        if (t < 128) {
            int c = s_lab[t];
            int rank = 0;
            for (int k = 0; k < t; k++) rank += (s_lab[k] == c);
            g_perm[g_classOff[c] + g_blockOff[bid][c] + rank] = bid * 128 + t;
        }
    }
    grid_barrier(3 * GRID);

    // =========== Phase D: tile tasks =====================================
    const int ntasks = g_ntasks;
    for (int task = bid; task < ntasks; task += GRID) {
        const int cls = g_taskC[task], it = g_taskI[task], jt = g_taskJ[task];
        const int off = g_classOff[cls];
        const int n = g_classOff[cls + 1] - off;

        __syncthreads();   // previous task fully consumed before overwriting tiles

        // ---- load: 2 threads per row (one per 64-k half); A duplicated ----
        if (t < 384) {
            int r2 = t >> 1;                 // 0..191
            int half = t & 1;
            int isB = r2 >= TI;
            int r = isB ? r2 - TI : r2;
            int gidx = (isB ? jt : it) + r;
            int row = g_perm[off + (gidx < n ? gidx : 0)];
            const float4* src = (const float4*)(x + row * DD + half * 64);
            float s = 0.f;
            if (!isB) {
                #pragma unroll
                for (int q = 0; q < 16; q++) {
                    float4 v = src[q];
                    s += v.x * v.x + v.y * v.y + v.z * v.z + v.w * v.w;
                    int k = half * 64 + 4 * q;
                    *(float2*)(At2 + (k + 0) * (2 * TI) + 2 * r) = make_float2(v.x, v.x);
                    *(float2*)(At2 + (k + 1) * (2 * TI) + 2 * r) = make_float2(v.y, v.y);
                    *(float2*)(At2 + (k + 2) * (2 * TI) + 2 * r) = make_float2(v.z, v.z);
                    *(float2*)(At2 + (k + 3) * (2 * TI) + 2 * r) = make_float2(v.w, v.w);
                }
            } else {
                #pragma unroll
                for (int q = 0; q < 16; q++) {
                    float4 v = src[q];
                    s += v.x * v.x + v.y * v.y + v.z * v.z + v.w * v.w;
                    int k = half * 64 + 4 * q;
                    Bt[(k + 0) * TI + r] = v.x;
                    Bt[(k + 1) * TI + r] = v.y;
                    Bt[(k + 2) * TI + r] = v.z;
                    Bt[(k + 3) * TI + r] = v.w;
                }
            }
            sqP[r2][half] = s;
        }
        __syncthreads();
        if (t < 2 * TI) s_sq[t] = sqP[t][0] + sqP[t][1];
        __syncthreads();

        // ---- 128-deep f32x2 micro-kernel: 6 LDS.64 + 9 FFMA2 per k ----
        // acc[i][jp] = { dot(i0+i, j0+2jp), dot(i0+i, j0+2jp+1) }
        ull acc[3][3];
        #pragma unroll
        for (int a = 0; a < 3; a++)
            #pragma unroll
            for (int b = 0; b < 3; b++) acc[a][b] = 0ull;

        #pragma unroll 4
        for (int k = 0; k < DD; k++) {
            const float* ar = At2 + k * (2 * TI) + 2 * i0;
            const float* br = Bt + k * TI + j0;
            ull a0 = *(const ull*)(ar);        // {a_i0,   a_i0}
            ull a1 = *(const ull*)(ar + 2);    // {a_i0+1, a_i0+1}
            ull a2 = *(const ull*)(ar + 4);
            ull b0 = *(const ull*)(br);        // {b_j0,   b_j0+1}
            ull b1 = *(const ull*)(br + 2);
            ull b2 = *(const ull*)(br + 4);
            asm("fma.rn.f32x2 %0, %1, %2, %0;" : "+l"(acc[0][0]) : "l"(a0), "l"(b0));
            asm("fma.rn.f32x2 %0, %1, %2, %0;" : "+l"(acc[0][1]) : "l"(a0), "l"(b1));
            asm("fma.rn.f32x2 %0, %1, %2, %0;" : "+l"(acc[0][2]) : "l"(a0), "l"(b2));
            asm("fma.rn.f32x2 %0, %1, %2, %0;" : "+l"(acc[1][0]) : "l"(a1), "l"(b0));
            asm("fma.rn.f32x2 %0, %1, %2, %0;" : "+l"(acc[1][1]) : "l"(a1), "l"(b1));
            asm("fma.rn.f32x2 %0, %1, %2, %0;" : "+l"(acc[1][2]) : "l"(a1), "l"(b2));
            asm("fma.rn.f32x2 %0, %1, %2, %0;" : "+l"(acc[2][0]) : "l"(a2), "l"(b0));
            asm("fma.rn.f32x2 %0, %1, %2, %0;" : "+l"(acc[2][1]) : "l"(a2), "l"(b1));
            asm("fma.rn.f32x2 %0, %1, %2, %0;" : "+l"(acc[2][2]) : "l"(a2), "l"(b2));
        }

        // ---- epilogue: d -> (hinge - d) over valid same-class pairs ----
        double lsum = 0.0;
        #pragma unroll
        for (int i = 0; i < 3; i++) {
            int gi = it + i0 + i;
            float sqa = s_sq[i0 + i];
            if (gi < n) {
                #pragma unroll
                for (int jp = 0; jp < 3; jp++) {
                    int gj = jt + j0 + 2 * jp;
                    float sbL = s_sq[TI + j0 + 2 * jp];
                    float sbH = s_sq[TI + j0 + 2 * jp + 1];
                    float dL = f2lo(acc[i][jp]), dH = f2hi(acc[i][jp]);
                    if (gj < n) {
                        float d = fmaxf(sqa + sbL - 2.f * dL, 0.f);
                        lsum += (double)(fmaxf(1.0f - d, 0.f) - d);
                    }
                    if (gj + 1 < n) {
                        float d = fmaxf(sqa + sbH - 2.f * dH, 0.f);
                        lsum += (double)(fmaxf(1.0f - d, 0.f) - d);
                    }
                }
            }
        }
        red[t] = lsum;
        __syncthreads();
        for (int s2 = 256; s2 > 0; s2 >>= 1) {
            if (t < s2) red[t] += red[t + s2];
            __syncthreads();
        }
        if (t == 0) g_tileRes[task] = red[0];
    }

    // =========== final combine: last block, deterministic fixed order =====
    if (t == 0) {
        __threadfence();
        int v = atomicAdd(&g_ticket, 1);
        s_isLast = (v == GRID - 1);
    }
    __syncthreads();
    if (s_isLast) {
        double mc = 0.0;
        if (t < 128) {
            #pragma unroll 8
            for (int b = 0; b < GRID; b++) mc += (double)g_partialM[b][t];
        }
        red[t] = mc * mc;
        __syncthreads();
        for (int s2 = 256; s2 > 0; s2 >>= 1) {
            if (t < s2) red[t] += red[t + s2];
            __syncthreads();
        }
        double msq = red[0];
        __syncthreads();
        double v = 0.0;
        for (int i = t; i < GRID; i += THREADS) v += 2.0 * (double)NN * g_partialS[i];
        for (int i = t; i < ntasks; i += THREADS) v += g_tileRes[i];
        red[t] = v;
        __syncthreads();
        for (int s2 = 256; s2 > 0; s2 >>= 1) {
            if (t < s2) red[t] += red[t + s2];
            __syncthreads();
        }
        if (t == 0) {
            double total = red[0] - 2.0 * msq;
            out[0] = (float)(total / ((double)NN * (double)NN));
            g_ticket = 0;
            g_barCnt = 0u;
        }
    }
}

extern "C" void kernel_launch(void* const* d_in, const int* in_sizes, int n_in,
                              void* d_out, int out_size) {
    const float* x = (const float*)d_in[0];
    const int* y32 = (const int*)d_in[1];

    static int attr_set = 0;
    if (!attr_set) {
        cudaFuncSetAttribute(k_main, cudaFuncAttributeMaxDynamicSharedMemorySize, SMEM_DYN);
        attr_set = 1;
    }
    k_main<<<GRID, THREADS, SMEM_DYN>>>(x, y32, (float*)d_out);
}

// round 10
// speedup vs baseline: 1.5388x; 1.5388x over previous
#include <cuda_runtime.h>

#define NN 8192
#define DD 128
#define CC 100
#define HBLK 64          // label chunks of 128 rows
#define GRID 148         // <= SM count -> all CTAs co-resident at occ 1
#define RPB 56           // ceil(NN/GRID) rows per block for stats
#define TI 96
#define THREADS 512
#define MAXT 7400
#define TASKB 64         // block that builds the task list
#define STATB 65         // block that folds stats into termAll
#define SMEM_DYN ((2 * TI + TI) * DD * 4)   // At2 (dup, 96KB) + Bt (48KB)

typedef unsigned long long ull;

// ---------------- device scratch (zero-init; counters self-reset) --------
__device__ int    g_counts[HBLK][CC];
__device__ int    g_classOff[CC + 1];
__device__ int    g_perm[NN];
__device__ int    g_taskC[MAXT], g_taskI[MAXT], g_taskJ[MAXT];
__device__ int    g_ntasks;
__device__ double g_tileRes[MAXT];
__device__ double g_partialS[GRID];
__device__ float  g_partialM[GRID][DD];
__device__ double g_termAll;
__device__ unsigned g_barCnt;
__device__ int    g_ticket;

__device__ __forceinline__ float f2lo(ull v) { return __uint_as_float((unsigned)v); }
__device__ __forceinline__ float f2hi(ull v) { return __uint_as_float((unsigned)(v >> 32)); }

__device__ __forceinline__ void grid_barrier(unsigned target) {
    __syncthreads();
    if (threadIdx.x == 0) {
        __threadfence();
        atomicAdd(&g_barCnt, 1u);
        while (atomicAdd(&g_barCnt, 0u) < target) { }
        __threadfence();
    }
    __syncthreads();
}

// int64 labels in [0,100) stored LE look like [v,0,v,0,...] as int32 words.
__device__ __forceinline__ int detect_mode(const int* y32, int t, int nthr) {
    __shared__ int s_mode;
    if (t == 0) s_mode = 1;
    __syncthreads();
    int bad = 0;
    for (int i = t; i < NN / 2; i += nthr)
        if (y32[2 * i + 1] != 0) bad = 1;
    if (bad) atomicExch(&s_mode, 0);
    __syncthreads();
    return s_mode;                 // 1 = int64, 0 = int32
}

__global__ void __launch_bounds__(THREADS, 1) k_main(const float* __restrict__ x,
                                                     const int* __restrict__ y32,
                                                     float* __restrict__ out) {
    extern __shared__ float dyn[];
    float* At2 = dyn;                    // [DD][2*TI], each value duplicated {v,v}
    float* Bt  = dyn + DD * 2 * TI;      // [DD][TI] k-major
    __shared__ float  sqP[2 * TI][2];
    __shared__ float  s_sq[2 * TI];
    __shared__ double red[THREADS];
    __shared__ float  s_sm[THREADS], s_ss[THREADS];
    __shared__ int    s_h[CC];
    __shared__ int    s_lab[128];
    __shared__ int    s_tot[CC], s_mine[CC], s_cls[CC];
    __shared__ int    s_isLast;

    const int t = threadIdx.x;
    const int bid = blockIdx.x;
    const int tx = t & 15, ty = t >> 4;   // ty 0..31
    const int i0 = ty * 3, j0 = tx * 6;

    // =========== Phase A: stats (contiguous rows) + label histogram =======
    {
        int c = t & 127, h = t >> 7;
        int base = bid * RPB;
        int lim = NN < base + RPB ? NN : base + RPB;
        float m = 0.f, s = 0.f;
        #pragma unroll
        for (int w = 0; w < (RPB + 3) / 4; w++) {
            int r = base + h + 4 * w;
            if (r < lim) { float v = x[r * DD + c]; m += v; s += v * v; }
        }
        s_sm[t] = m; s_ss[t] = s;
        __syncthreads();
        if (t < 128) g_partialM[bid][t] = s_sm[t] + s_sm[t + 128] + s_sm[t + 256] + s_sm[t + 384];
        for (int s2 = 256; s2 > 0; s2 >>= 1) {
            if (t < s2) s_ss[t] += s_ss[t + s2];
            __syncthreads();
        }
        if (t == 0) g_partialS[bid] = (double)s_ss[0];
    }
    int mode = 1;
    if (bid < HBLK) {
        mode = detect_mode(y32, t, THREADS);
        if (t < CC) s_h[t] = 0;
        __syncthreads();
        if (t < 128) {
            int i = bid * 128 + t;
            int c = mode ? y32[2 * i] : y32[i];
            atomicAdd(&s_h[c], 1);
        }
        __syncthreads();
        if (t < CC) g_counts[bid][t] = s_h[t];
    }
    grid_barrier(GRID);

    // ====== Phase B/C (parallel): scatter | task list | termAll ==========
    if (bid < HBLK) {
        // local offsets via fully-unrolled independent loads (MLP=64)
        if (t < CC) {
            int tot = 0, mine = 0;
            #pragma unroll
            for (int b = 0; b < HBLK; b++) {
                int v = g_counts[b][t];
                tot += v;
                mine += (b < bid) ? v : 0;
            }
            s_tot[t] = tot; s_mine[t] = mine;
        }
        if (t < 128) {
            int i = bid * 128 + t;
            s_lab[t] = mode ? y32[2 * i] : y32[i];
        }
        __syncthreads();
        if (t == 0) {
            int run = 0;
            for (int c = 0; c < CC; c++) { s_cls[c] = run; run += s_tot[c]; }
        }
        __syncthreads();
        if (t < 128) {
            int c = s_lab[t];
            int rank = 0;
            for (int k = 0; k < t; k++) rank += (s_lab[k] == c);
            g_perm[s_cls[c] + s_mine[c] + rank] = bid * 128 + t;
        }
    } else if (bid == TASKB) {
        if (t < CC) {
            int tot = 0;
            #pragma unroll
            for (int b = 0; b < HBLK; b++) tot += g_counts[b][t];
            s_tot[t] = tot;
        }
        __syncthreads();
        if (t == 0) {
            int run = 0;
            for (int c = 0; c < CC; c++) { g_classOff[c] = run; run += s_tot[c]; }
            g_classOff[CC] = run;
            int nt = 0;
            for (int c = 0; c < CC; c++) {
                int m2 = (s_tot[c] + TI - 1) / TI;
                for (int a = 0; a < m2 && nt < MAXT; a++)
                    for (int b = 0; b < m2 && nt < MAXT; b++) {
                        g_taskC[nt] = c; g_taskI[nt] = a * TI; g_taskJ[nt] = b * TI; nt++;
                    }
            }
            g_ntasks = nt;
        }
    } else if (bid == STATB) {
        // termAll = 2N*S - 2*||m||^2, computed while others scatter
        double mc0 = 0.0, mc1 = 0.0;
        if (t < 128) {
            #pragma unroll
            for (int b = 0; b < GRID; b += 2) {
                mc0 += (double)g_partialM[b][t];
                if (b + 1 < GRID) mc1 += (double)g_partialM[b + 1][t];
            }
        }
        double mc = mc0 + mc1;
        red[t] = (t < 128) ? mc * mc : 0.0;
        __syncthreads();
        for (int s2 = 256; s2 > 0; s2 >>= 1) {
            if (t < s2) red[t] += red[t + s2];
            __syncthreads();
        }
        double msq = red[0];
        __syncthreads();
        red[t] = (t < GRID) ? g_partialS[t] : 0.0;
        __syncthreads();
        for (int s2 = 256; s2 > 0; s2 >>= 1) {
            if (t < s2) red[t] += red[t + s2];
            __syncthreads();
        }
        if (t == 0) g_termAll = 2.0 * (double)NN * red[0] - 2.0 * msq;
    }
    grid_barrier(2 * GRID);

    // =========== Phase D: tile tasks =====================================
    const int ntasks = g_ntasks;
    for (int task = bid; task < ntasks; task += GRID) {
        const int cls = g_taskC[task], it = g_taskI[task], jt = g_taskJ[task];
        const int off = g_classOff[cls];
        const int n = g_classOff[cls + 1] - off;

        __syncthreads();

        // ---- load: 2 threads per row (one per 64-k half); A duplicated ----
        if (t < 384) {
            int r2 = t >> 1;
            int half = t & 1;
            int isB = r2 >= TI;
            int r = isB ? r2 - TI : r2;
            int gidx = (isB ? jt : it) + r;
            int row = g_perm[off + (gidx < n ? gidx : 0)];
            const float4* src = (const float4*)(x + row * DD + half * 64);
            float s = 0.f;
            if (!isB) {
                #pragma unroll
                for (int q = 0; q < 16; q++) {
                    float4 v = src[q];
                    s += v.x * v.x + v.y * v.y + v.z * v.z + v.w * v.w;
                    int k = half * 64 + 4 * q;
                    *(float2*)(At2 + (k + 0) * (2 * TI) + 2 * r) = make_float2(v.x, v.x);
                    *(float2*)(At2 + (k + 1) * (2 * TI) + 2 * r) = make_float2(v.y, v.y);
                    *(float2*)(At2 + (k + 2) * (2 * TI) + 2 * r) = make_float2(v.z, v.z);
                    *(float2*)(At2 + (k + 3) * (2 * TI) + 2 * r) = make_float2(v.w, v.w);
                }
            } else {
                #pragma unroll
                for (int q = 0; q < 16; q++) {
                    float4 v = src[q];
                    s += v.x * v.x + v.y * v.y + v.z * v.z + v.w * v.w;
                    int k = half * 64 + 4 * q;
                    Bt[(k + 0) * TI + r] = v.x;
                    Bt[(k + 1) * TI + r] = v.y;
                    Bt[(k + 2) * TI + r] = v.z;
                    Bt[(k + 3) * TI + r] = v.w;
                }
            }
            sqP[r2][half] = s;
        }
        __syncthreads();
        if (t < 2 * TI) s_sq[t] = sqP[t][0] + sqP[t][1];
        __syncthreads();

        // ---- 128-deep f32x2 micro-kernel: 6 LDS.64 + 9 FFMA2 per k ----
        ull acc[3][3];
        #pragma unroll
        for (int a = 0; a < 3; a++)
            #pragma unroll
            for (int b = 0; b < 3; b++) acc[a][b] = 0ull;

        #pragma unroll 4
        for (int k = 0; k < DD; k++) {
            const float* ar = At2 + k * (2 * TI) + 2 * i0;
            const float* br = Bt + k * TI + j0;
            ull a0 = *(const ull*)(ar);
            ull a1 = *(const ull*)(ar + 2);
            ull a2 = *(const ull*)(ar + 4);
            ull b0 = *(const ull*)(br);
            ull b1 = *(const ull*)(br + 2);
            ull b2 = *(const ull*)(br + 4);
            asm("fma.rn.f32x2 %0, %1, %2, %0;" : "+l"(acc[0][0]) : "l"(a0), "l"(b0));
            asm("fma.rn.f32x2 %0, %1, %2, %0;" : "+l"(acc[0][1]) : "l"(a0), "l"(b1));
            asm("fma.rn.f32x2 %0, %1, %2, %0;" : "+l"(acc[0][2]) : "l"(a0), "l"(b2));
            asm("fma.rn.f32x2 %0, %1, %2, %0;" : "+l"(acc[1][0]) : "l"(a1), "l"(b0));
            asm("fma.rn.f32x2 %0, %1, %2, %0;" : "+l"(acc[1][1]) : "l"(a1), "l"(b1));
            asm("fma.rn.f32x2 %0, %1, %2, %0;" : "+l"(acc[1][2]) : "l"(a1), "l"(b2));
            asm("fma.rn.f32x2 %0, %1, %2, %0;" : "+l"(acc[2][0]) : "l"(a2), "l"(b0));
            asm("fma.rn.f32x2 %0, %1, %2, %0;" : "+l"(acc[2][1]) : "l"(a2), "l"(b1));
            asm("fma.rn.f32x2 %0, %1, %2, %0;" : "+l"(acc[2][2]) : "l"(a2), "l"(b2));
        }

        // ---- epilogue ----
        double lsum = 0.0;
        #pragma unroll
        for (int i = 0; i < 3; i++) {
            int gi = it + i0 + i;
            float sqa = s_sq[i0 + i];
            if (gi < n) {
                #pragma unroll
                for (int jp = 0; jp < 3; jp++) {
                    int gj = jt + j0 + 2 * jp;
                    float sbL = s_sq[TI + j0 + 2 * jp];
                    float sbH = s_sq[TI + j0 + 2 * jp + 1];
                    float dL = f2lo(acc[i][jp]), dH = f2hi(acc[i][jp]);
                    if (gj < n) {
                        float d = fmaxf(sqa + sbL - 2.f * dL, 0.f);
                        lsum += (double)(fmaxf(1.0f - d, 0.f) - d);
                    }
                    if (gj + 1 < n) {
                        float d = fmaxf(sqa + sbH - 2.f * dH, 0.f);
                        lsum += (double)(fmaxf(1.0f - d, 0.f) - d);
                    }
                }
            }
        }
        red[t] = lsum;
        __syncthreads();
        for (int s2 = 256; s2 > 0; s2 >>= 1) {
            if (t < s2) red[t] += red[t + s2];
            __syncthreads();
        }
        if (t == 0) g_tileRes[task] = red[0];
    }

    // =========== final: last block sums tileRes + termAll ================
    if (t == 0) {
        __threadfence();
        int v = atomicAdd(&g_ticket, 1);
        s_isLast = (v == GRID - 1);
    }
    __syncthreads();
    if (s_isLast) {
        double v = 0.0;
        for (int i = t; i < ntasks; i += THREADS) v += g_tileRes[i];
        red[t] = v;
        __syncthreads();
        for (int s2 = 256; s2 > 0; s2 >>= 1) {
            if (t < s2) red[t] += red[t + s2];
            __syncthreads();
        }
        if (t == 0) {
            double total = red[0] + g_termAll;
            out[0] = (float)(total / ((double)NN * (double)NN));
            g_ticket = 0;
            g_barCnt = 0u;
        }
    }
}

extern "C" void kernel_launch(void* const* d_in, const int* in_sizes, int n_in,
                              void* d_out, int out_size) {
    const float* x = (const float*)d_in[0];
    const int* y32 = (const int*)d_in[1];

    static int attr_set = 0;
    if (!attr_set) {
        cudaFuncSetAttribute(k_main, cudaFuncAttributeMaxDynamicSharedMemorySize, SMEM_DYN);
        attr_set = 1;
    }
    k_main<<<GRID, THREADS, SMEM_DYN>>>(x, y32, (float*)d_out);
}

// round 12
// speedup vs baseline: 1.5825x; 1.0284x over previous
#include <cuda_runtime.h>

#define NN 8192
#define DD 128
#define CC 100
#define HBLK 64          // label chunks of 128 rows (blocks 0..63)
#define TASKB 64         // block that builds the task list
#define GRID 148         // <= SM count -> all CTAs co-resident at occ 1
#define TI 96
#define THREADS 512
#define MAXT 7400
#define AS 196           // At2 row stride in words (EVEN: keeps LDS.64 aligned)
#define BS 98            // Bt row stride in words (EVEN)
#define SMEM_DYN ((AS + BS) * DD * 4)   // 147 KB

typedef unsigned long long ull;

// ---------------- device scratch (zero-init; counters self-reset) --------
__device__ int    g_counts[HBLK][CC];
__device__ int    g_classOff[CC + 1];
__device__ int    g_perm[NN];
__device__ int    g_taskC[MAXT], g_taskI[MAXT], g_taskJ[MAXT];
__device__ int    g_ntasks;
__device__ double g_tileRes[MAXT];
__device__ double g_partialS[GRID];
__device__ float  g_partialM[GRID][DD];
__device__ unsigned g_bar1, g_bar2;
__device__ int    g_ticket;

__device__ __forceinline__ float f2lo(ull v) { return __uint_as_float((unsigned)v); }
__device__ __forceinline__ float f2hi(ull v) { return __uint_as_float((unsigned)(v >> 32)); }

// arrival: fence + atomic increment. polling: plain volatile loads (no LTS
// atomic-ALU serialization) with nanosleep backoff.
__device__ __forceinline__ void bar_arrive(unsigned* ctr) {
    __threadfence();
    atomicAdd(ctr, 1u);
}
__device__ __forceinline__ void bar_poll(unsigned* ctr, unsigned target) {
    volatile unsigned* p = (volatile unsigned*)ctr;
    if (*p < target) {
        while (*p < target) __nanosleep(128);
    }
    __threadfence();
}

// int64 labels in [0,100) stored LE look like [v,0,v,0,...] as int32 words.
__device__ __forceinline__ int detect_mode(const int* y32, int t, int nthr) {
    __shared__ int s_mode;
    if (t == 0) s_mode = 1;
    __syncthreads();
    int bad = 0;
    for (int i = t; i < NN / 2; i += nthr)
        if (y32[2 * i + 1] != 0) bad = 1;
    if (bad) atomicExch(&s_mode, 0);
    __syncthreads();
    return s_mode;                 // 1 = int64, 0 = int32
}

__global__ void __launch_bounds__(THREADS, 1) k_main(const float* __restrict__ x,
                                                     const int* __restrict__ y32,
                                                     float* __restrict__ out) {
    extern __shared__ float dyn[];
    float* At2 = dyn;                    // [DD][AS], values duplicated {v,v} at 2*r
    float* Bt  = dyn + DD * AS;          // [DD][BS] k-major
    __shared__ float  sqP[2 * TI][2];
    __shared__ float  s_sq[2 * TI];
    __shared__ double red[THREADS];
    __shared__ float  s_sm[THREADS], s_ss[THREADS];
    __shared__ int    s_h[CC];
    __shared__ int    s_lab[128];
    __shared__ int    s_tot[CC], s_mine[CC], s_cls[CC];
    __shared__ int    s_isLast;

    const int t = threadIdx.x;
    const int bid = blockIdx.x;
    const int tx = t & 15, ty = t >> 4;   // ty 0..31
    const int i0 = ty * 3, j0 = tx * 6;

    // =========== label pipeline: blocks 0..64 only ========================
    if (bid < HBLK) {
        int mode = detect_mode(y32, t, THREADS);
        if (t < CC) s_h[t] = 0;
        __syncthreads();
        if (t < 128) {
            int i = bid * 128 + t;
            int c = mode ? y32[2 * i] : y32[i];
            s_lab[t] = c;
            atomicAdd(&s_h[c], 1);
        }
        __syncthreads();
        if (t < CC) g_counts[bid][t] = s_h[t];
        __syncthreads();
        if (t == 0) { bar_arrive(&g_bar1); bar_poll(&g_bar1, HBLK); }
        __syncthreads();
        // local offsets via fully-unrolled independent loads (MLP=64)
        if (t < CC) {
            int tot = 0, mine = 0;
            #pragma unroll
            for (int b = 0; b < HBLK; b++) {
                int v = g_counts[b][t];
                tot += v;
                mine += (b < bid) ? v : 0;
            }
            s_tot[t] = tot; s_mine[t] = mine;
        }
        __syncthreads();
        if (t == 0) {
            int run = 0;
            for (int c = 0; c < CC; c++) { s_cls[c] = run; run += s_tot[c]; }
        }
        __syncthreads();
        if (t < 128) {
            int c = s_lab[t];
            int rank = 0;
            for (int k = 0; k < t; k++) rank += (s_lab[k] == c);
            g_perm[s_cls[c] + s_mine[c] + rank] = bid * 128 + t;
        }
        __syncthreads();
        if (t == 0) bar_arrive(&g_bar2);
    } else if (bid == TASKB) {
        if (t == 0) bar_poll(&g_bar1, HBLK);
        __syncthreads();
        if (t < CC) {
            int tot = 0;
            #pragma unroll
            for (int b = 0; b < HBLK; b++) tot += g_counts[b][t];
            s_tot[t] = tot;
        }
        __syncthreads();
        if (t == 0) {
            int run = 0;
            for (int c = 0; c < CC; c++) { g_classOff[c] = run; run += s_tot[c]; }
            g_classOff[CC] = run;
            int nt = 0;
            for (int c = 0; c < CC; c++) {
                int m2 = (s_tot[c] + TI - 1) / TI;
                for (int a = 0; a < m2 && nt < MAXT; a++)
                    for (int b = 0; b < m2 && nt < MAXT; b++) {
                        g_taskC[nt] = c; g_taskI[nt] = a * TI; g_taskJ[nt] = b * TI; nt++;
                    }
            }
            g_ntasks = nt;
            bar_arrive(&g_bar2);
        }
    }

    // =========== all blocks wait for scatter + task list ==================
    if (t == 0) bar_poll(&g_bar2, HBLK + 1);
    __syncthreads();
    const int ntasks = g_ntasks;

    // =========== Phase D: tile tasks =====================================
    for (int task = bid; task < ntasks; task += GRID) {
        const int cls = g_taskC[task], it = g_taskI[task], jt = g_taskJ[task];
        const int off = g_classOff[cls];
        const int n = g_classOff[cls + 1] - off;

        __syncthreads();   // previous task fully consumed before overwrite

        // ---- load: 2 threads/row, interleaved float4 halves (q = 2w+h) ---
        if (t < 384) {
            int r2 = t >> 1;
            int h = t & 1;
            int isB = r2 >= TI;
            int r = isB ? r2 - TI : r2;
            int gidx = (isB ? jt : it) + r;
            int row = g_perm[off + (gidx < n ? gidx : 0)];
            const float4* src = (const float4*)(x + row * DD);
            float s = 0.f;
            if (!isB) {
                #pragma unroll
                for (int w = 0; w < 16; w++) {
                    int q = 2 * w + h;
                    float4 v = src[q];
                    s += v.x * v.x + v.y * v.y + v.z * v.z + v.w * v.w;
                    int k = 4 * q;
                    *(float2*)(At2 + (k + 0) * AS + 2 * r) = make_float2(v.x, v.x);
                    *(float2*)(At2 + (k + 1) * AS + 2 * r) = make_float2(v.y, v.y);
                    *(float2*)(At2 + (k + 2) * AS + 2 * r) = make_float2(v.z, v.z);
                    *(float2*)(At2 + (k + 3) * AS + 2 * r) = make_float2(v.w, v.w);
                }
            } else {
                #pragma unroll
                for (int w = 0; w < 16; w++) {
                    int q = 2 * w + h;
                    float4 v = src[q];
                    s += v.x * v.x + v.y * v.y + v.z * v.z + v.w * v.w;
                    int k = 4 * q;
                    Bt[(k + 0) * BS + r] = v.x;
                    Bt[(k + 1) * BS + r] = v.y;
                    Bt[(k + 2) * BS + r] = v.z;
                    Bt[(k + 3) * BS + r] = v.w;
                }
            }
            sqP[r2][h] = s;
        }
        __syncthreads();
        if (t < 2 * TI) s_sq[t] = sqP[t][0] + sqP[t][1];
        __syncthreads();

        // ---- 128-deep f32x2 micro-kernel: 6 LDS + 9 FFMA2 per k ----
        ull acc[3][3];
        #pragma unroll
        for (int a = 0; a < 3; a++)
            #pragma unroll
            for (int b = 0; b < 3; b++) acc[a][b] = 0ull;

        #pragma unroll 8
        for (int k = 0; k < DD; k++) {
            const float* ar = At2 + k * AS + 2 * i0;
            const float* br = Bt + k * BS + j0;
            ull a0 = *(const ull*)(ar);
            ull a1 = *(const ull*)(ar + 2);
            ull a2 = *(const ull*)(ar + 4);
            ull b0 = *(const ull*)(br);
            ull b1 = *(const ull*)(br + 2);
            ull b2 = *(const ull*)(br + 4);
            asm("fma.rn.f32x2 %0, %1, %2, %0;" : "+l"(acc[0][0]) : "l"(a0), "l"(b0));
            asm("fma.rn.f32x2 %0, %1, %2, %0;" : "+l"(acc[0][1]) : "l"(a0), "l"(b1));
            asm("fma.rn.f32x2 %0, %1, %2, %0;" : "+l"(acc[0][2]) : "l"(a0), "l"(b2));
            asm("fma.rn.f32x2 %0, %1, %2, %0;" : "+l"(acc[1][0]) : "l"(a1), "l"(b0));
            asm("fma.rn.f32x2 %0, %1, %2, %0;" : "+l"(acc[1][1]) : "l"(a1), "l"(b1));
            asm("fma.rn.f32x2 %0, %1, %2, %0;" : "+l"(acc[1][2]) : "l"(a1), "l"(b2));
            asm("fma.rn.f32x2 %0, %1, %2, %0;" : "+l"(acc[2][0]) : "l"(a2), "l"(b0));
            asm("fma.rn.f32x2 %0, %1, %2, %0;" : "+l"(acc[2][1]) : "l"(a2), "l"(b1));
            asm("fma.rn.f32x2 %0, %1, %2, %0;" : "+l"(acc[2][2]) : "l"(a2), "l"(b2));
        }

        // ---- epilogue ----
        double lsum = 0.0;
        #pragma unroll
        for (int i = 0; i < 3; i++) {
            int gi = it + i0 + i;
            float sqa = s_sq[i0 + i];
            if (gi < n) {
                #pragma unroll
                for (int jp = 0; jp < 3; jp++) {
                    int gj = jt + j0 + 2 * jp;
                    float sbL = s_sq[TI + j0 + 2 * jp];
                    float sbH = s_sq[TI + j0 + 2 * jp + 1];
                    float dL = f2lo(acc[i][jp]), dH = f2hi(acc[i][jp]);
                    if (gj < n) {
                        float d = fmaxf(sqa + sbL - 2.f * dL, 0.f);
                        lsum += (double)(fmaxf(1.0f - d, 0.f) - d);
                    }
                    if (gj + 1 < n) {
                        float d = fmaxf(sqa + sbH - 2.f * dH, 0.f);
                        lsum += (double)(fmaxf(1.0f - d, 0.f) - d);
                    }
                }
            }
        }
        red[t] = lsum;
        __syncthreads();
        for (int s2 = 256; s2 > 0; s2 >>= 1) {
            if (t < s2) red[t] += red[t + s2];
            __syncthreads();
        }
        if (t == 0) g_tileRes[task] = red[0];
    }

    // =========== stats: task-free blocks, concurrent with phase D =========
    const int SSTART = (ntasks < GRID - 8) ? ntasks : (GRID - 8);
    const int nslice = GRID - SSTART;
    if (bid >= SSTART) {
        int s = bid - SSTART;
        int r0 = (s * NN) / nslice, r1 = ((s + 1) * NN) / nslice;
        int c = t & 127, h4 = t >> 7;
        float m = 0.f, sq = 0.f;
        #pragma unroll 4
        for (int r = r0 + h4; r < r1; r += 4) {
            float v = x[r * DD + c];
            m += v; sq += v * v;
        }
        s_sm[t] = m; s_ss[t] = sq;
        __syncthreads();
        if (t < 128) g_partialM[s][t] = s_sm[t] + s_sm[t + 128] + s_sm[t + 256] + s_sm[t + 384];
        for (int s2 = 256; s2 > 0; s2 >>= 1) {
            if (t < s2) s_ss[t] += s_ss[t + s2];
            __syncthreads();
        }
        if (t == 0) g_partialS[s] = (double)s_ss[0];
    }

    // =========== final: last block combines everything ====================
    if (t == 0) {
        __threadfence();
        int v = atomicAdd(&g_ticket, 1);
        s_isLast = (v == GRID - 1);
    }
    __syncthreads();
    if (s_isLast) {
        // ||m||^2 from nslice column-sum slices
        double mc = 0.0;
        if (t < 128) {
            #pragma unroll 4
            for (int b = 0; b < nslice; b++) mc += (double)g_partialM[b][t];
        }
        red[t] = (t < 128) ? mc * mc : 0.0;
        __syncthreads();
        for (int s2 = 256; s2 > 0; s2 >>= 1) {
            if (t < s2) red[t] += red[t + s2];
            __syncthreads();
        }
        double msq = red[0];
        __syncthreads();
        // 2N*S + tile contributions
        double v = 0.0;
        for (int i = t; i < nslice; i += THREADS) v += 2.0 * (double)NN * g_partialS[i];
        for (int i = t; i < ntasks; i += THREADS) v += g_tileRes[i];
        red[t] = v;
        __syncthreads();
        for (int s2 = 256; s2 > 0; s2 >>= 1) {
            if (t < s2) red[t] += red[t + s2];
            __syncthreads();
        }
        if (t == 0) {
            double total = red[0] - 2.0 * msq;
            out[0] = (float)(total / ((double)NN * (double)NN));
            g_ticket = 0;          // reset for next graph replay
            g_bar1 = 0u;
            g_bar2 = 0u;
        }
    }
}

extern "C" void kernel_launch(void* const* d_in, const int* in_sizes, int n_in,
                              void* d_out, int out_size) {
    const float* x = (const float*)d_in[0];
    const int* y32 = (const int*)d_in[1];

    static int attr_set = 0;
    if (!attr_set) {
        cudaFuncSetAttribute(k_main, cudaFuncAttributeMaxDynamicSharedMemorySize, SMEM_DYN);
        attr_set = 1;
    }
    k_main<<<GRID, THREADS, SMEM_DYN>>>(x, y32, (float*)d_out);
}

// round 16
// speedup vs baseline: 1.5886x; 1.0039x over previous
#include <cuda_runtime.h>

#define NN 8192
#define DD 128
#define CC 100
#define HBLK 64          // label chunks of 128 rows (blocks 0..63)
#define TASKB 64         // block that builds the task list
#define GRID 148
#define TI 96
#define THREADS 768
#define MAXT 7400
#define AS 196           // At2 row stride (words): 192 dup + 4 pad, %4==0
#define BS 98            // Bt row stride (words): 96 + 2 pad, even
#define SMEM_DYN ((AS + BS) * DD * 4)   // 147 KB

typedef unsigned long long ull;

__device__ int    g_counts[HBLK][CC];
__device__ int    g_classOff[CC + 1];
__device__ int    g_perm[NN];
__device__ int    g_taskC[MAXT], g_taskI[MAXT], g_taskJ[MAXT];
__device__ int    g_ntasks;
__device__ double g_tileRes[MAXT];
__device__ double g_partialS[GRID];
__device__ float  g_partialM[GRID][DD];
__device__ unsigned g_bar1, g_bar2;
__device__ int    g_ticket;

__device__ __forceinline__ float f2lo(ull v) { return __uint_as_float((unsigned)v); }
__device__ __forceinline__ float f2hi(ull v) { return __uint_as_float((unsigned)(v >> 32)); }

__device__ __forceinline__ void bar_arrive(unsigned* ctr) {
    __threadfence();
    atomicAdd(ctr, 1u);
}
__device__ __forceinline__ void bar_poll(unsigned* ctr, unsigned target) {
    volatile unsigned* p = (volatile unsigned*)ctr;
    if (*p < target) {
        while (*p < target) __nanosleep(128);
    }
    __threadfence();
}

// int64 labels in [0,100) stored LE look like [v,0,v,0,...] as int32 words.
__device__ __forceinline__ int detect_mode(const int* y32, int t) {
    __shared__ int s_mode;
    if (t == 0) s_mode = 1;
    __syncthreads();
    int bad = 0;
    for (int i = t; i < NN / 2; i += THREADS)
        if (y32[2 * i + 1] != 0) bad = 1;
    if (bad) atomicExch(&s_mode, 0);
    __syncthreads();
    return s_mode;
}

__device__ __forceinline__ double warp_red(double v) {
    #pragma unroll
    for (int o = 16; o > 0; o >>= 1)
        v += __shfl_down_sync(0xffffffffu, v, o);
    return v;
}

__global__ void __launch_bounds__(THREADS, 1) k_main(const float* __restrict__ x,
                                                     const int* __restrict__ y32,
                                                     float* __restrict__ out) {
    extern __shared__ float dyn[];
    float* At2 = dyn;                    // [DD][AS], values duplicated {v,v} at 2*r
    float* Bt  = dyn + DD * AS;          // [DD][BS]
    __shared__ float  sqP[2 * TI][4];
    __shared__ float  s_sq[2 * TI];
    __shared__ double s_red[32];
    __shared__ float  s_sm[THREADS], s_ss[THREADS];
    __shared__ int    s_h[CC];
    __shared__ int    s_lab[128];
    __shared__ int    s_tot[CC], s_mine[CC], s_cls[CC];
    __shared__ int    s_isLast;

    const int t = threadIdx.x;
    const int bid = blockIdx.x;
    const int lane = t & 31;
    const int w = t >> 5;                       // warp 0..23
    const int tx = t & 15, ty = t >> 4;         // ty 0..47
    const int i0 = 2 * ty, j0 = 6 * tx;

    // =========== label pipeline: blocks 0..64 =============================
    if (bid < HBLK) {
        int mode = detect_mode(y32, t);
        if (t < CC) s_h[t] = 0;
        __syncthreads();
        if (t < 128) {
            int i = bid * 128 + t;
            int c = mode ? y32[2 * i] : y32[i];
            s_lab[t] = c;
            atomicAdd(&s_h[c], 1);
        }
        __syncthreads();
        if (t < CC) g_counts[bid][t] = s_h[t];
        __syncthreads();
        if (t == 0) { bar_arrive(&g_bar1); bar_poll(&g_bar1, HBLK); }
        __syncthreads();
        if (t < CC) {
            int tot = 0, mine = 0;
            #pragma unroll
            for (int b = 0; b < HBLK; b++) {
                int v = g_counts[b][t];
                tot += v;
                mine += (b < bid) ? v : 0;
            }
            s_tot[t] = tot; s_mine[t] = mine;
        }
        __syncthreads();
        if (t == 0) {
            int run = 0;
            for (int c = 0; c < CC; c++) { s_cls[c] = run; run += s_tot[c]; }
        }
        __syncthreads();
        if (t < 128) {
            int c = s_lab[t];
            int rank = 0;
            for (int k = 0; k < t; k++) rank += (s_lab[k] == c);
            g_perm[s_cls[c] + s_mine[c] + rank] = bid * 128 + t;
        }
        __syncthreads();
        if (t == 0) bar_arrive(&g_bar2);
    } else if (bid == TASKB) {
        if (t == 0) bar_poll(&g_bar1, HBLK);
        __syncthreads();
        if (t < CC) {
            int tot = 0;
            #pragma unroll
            for (int b = 0; b < HBLK; b++) tot += g_counts[b][t];
            s_tot[t] = tot;
        }
        __syncthreads();
        if (t == 0) {
            int run = 0;
            for (int c = 0; c < CC; c++) { g_classOff[c] = run; run += s_tot[c]; }
            g_classOff[CC] = run;
            int nt = 0;
            for (int c = 0; c < CC; c++) {
                int m2 = (s_tot[c] + TI - 1) / TI;
                for (int a = 0; a < m2 && nt < MAXT; a++)
                    for (int b = 0; b < m2 && nt < MAXT; b++) {
                        g_taskC[nt] = c; g_taskI[nt] = a * TI; g_taskJ[nt] = b * TI; nt++;
                    }
            }
            g_ntasks = nt;
            bar_arrive(&g_bar2);
        }
    }

    if (t == 0) bar_poll(&g_bar2, HBLK + 1);
    __syncthreads();
    const int ntasks = g_ntasks;

    // =========== Phase D: tile tasks =====================================
    for (int task = bid; task < ntasks; task += GRID) {
        const int cls = g_taskC[task], it = g_taskI[task], jt = g_taskJ[task];
        const int off = g_classOff[cls];
        const int n = g_classOff[cls + 1] - off;

        __syncthreads();   // previous tile fully consumed before overwrite

        // ---- load: 4 threads/row (all 768 threads), transposed stores ----
        {
            int r2 = t >> 2;                 // 0..191
            int h = t & 3;                   // quarter selector
            int isB = r2 >= TI;
            int r = isB ? r2 - TI : r2;
            int gidx = (isB ? jt : it) + r;
            int row = g_perm[off + (gidx < n ? gidx : 0)];
            const float4* src = (const float4*)(x + row * DD);
            float s = 0.f;
            if (!isB) {
                #pragma unroll
                for (int q8 = 0; q8 < 8; q8++) {
                    int q = h + 4 * q8;      // 0..31
                    float4 v = src[q];
                    s += v.x * v.x + v.y * v.y + v.z * v.z + v.w * v.w;
                    int k = 4 * q;
                    *(float2*)(At2 + (k + 0) * AS + 2 * r) = make_float2(v.x, v.x);
                    *(float2*)(At2 + (k + 1) * AS + 2 * r) = make_float2(v.y, v.y);
                    *(float2*)(At2 + (k + 2) * AS + 2 * r) = make_float2(v.z, v.z);
                    *(float2*)(At2 + (k + 3) * AS + 2 * r) = make_float2(v.w, v.w);
                }
            } else {
                #pragma unroll
                for (int q8 = 0; q8 < 8; q8++) {
                    int q = h + 4 * q8;
                    float4 v = src[q];
                    s += v.x * v.x + v.y * v.y + v.z * v.z + v.w * v.w;
                    int k = 4 * q;
                    Bt[(k + 0) * BS + r] = v.x;
                    Bt[(k + 1) * BS + r] = v.y;
                    Bt[(k + 2) * BS + r] = v.z;
                    Bt[(k + 3) * BS + r] = v.w;
                }
            }
            sqP[r2][h] = s;
        }
        __syncthreads();
        if (t < 2 * TI) s_sq[t] = (sqP[t][0] + sqP[t][1]) + (sqP[t][2] + sqP[t][3]);
        __syncthreads();

        // ---- 128-deep f32x2: 1 LDS.128 + 3 LDS.64 + 6 FFMA2 per k ----
        ull acc[2][3];
        #pragma unroll
        for (int p = 0; p < 2; p++)
            #pragma unroll
            for (int c = 0; c < 3; c++) acc[p][c] = 0ull;

        #pragma unroll 8
        for (int k = 0; k < DD; k++) {
            const float* ab = At2 + k * AS + 4 * ty;
            const float* bb = Bt + k * BS + j0;
            ulonglong2 av = *(const ulonglong2*)ab;   // {a_i0 dup, a_i0+1 dup}
            ull b0 = *(const ull*)(bb);
            ull b1 = *(const ull*)(bb + 2);
            ull b2 = *(const ull*)(bb + 4);
            asm("fma.rn.f32x2 %0, %1, %2, %0;" : "+l"(acc[0][0]) : "l"(av.x), "l"(b0));
            asm("fma.rn.f32x2 %0, %1, %2, %0;" : "+l"(acc[0][1]) : "l"(av.x), "l"(b1));
            asm("fma.rn.f32x2 %0, %1, %2, %0;" : "+l"(acc[0][2]) : "l"(av.x), "l"(b2));
            asm("fma.rn.f32x2 %0, %1, %2, %0;" : "+l"(acc[1][0]) : "l"(av.y), "l"(b0));
            asm("fma.rn.f32x2 %0, %1, %2, %0;" : "+l"(acc[1][1]) : "l"(av.y), "l"(b1));
            asm("fma.rn.f32x2 %0, %1, %2, %0;" : "+l"(acc[1][2]) : "l"(av.y), "l"(b2));
        }

        // ---- epilogue ----
        double lsum = 0.0;
        #pragma unroll
        for (int p = 0; p < 2; p++) {
            int gi = it + i0 + p;
            float sqa = s_sq[i0 + p];
            if (gi < n) {
                #pragma unroll
                for (int c = 0; c < 3; c++) {
                    int gj = jt + j0 + 2 * c;
                    float sbL = s_sq[TI + j0 + 2 * c];
                    float sbH = s_sq[TI + j0 + 2 * c + 1];
                    float dL = f2lo(acc[p][c]), dH = f2hi(acc[p][c]);
                    if (gj < n) {
                        float d = fmaxf(sqa + sbL - 2.f * dL, 0.f);
                        lsum += (double)(fmaxf(1.0f - d, 0.f) - d);
                    }
                    if (gj + 1 < n) {
                        float d = fmaxf(sqa + sbH - 2.f * dH, 0.f);
                        lsum += (double)(fmaxf(1.0f - d, 0.f) - d);
                    }
                }
            }
        }
        lsum = warp_red(lsum);
        if (lane == 0) s_red[w] = lsum;
        __syncthreads();
        if (w == 0) {
            double v = (lane < 24) ? s_red[lane] : 0.0;
            v = warp_red(v);
            if (lane == 0) g_tileRes[task] = v;
        }
    }

    // =========== stats: task-free blocks, concurrent with phase D =========
    const int SSTART = (ntasks < GRID - 8) ? ntasks : (GRID - 8);
    const int nslice = GRID - SSTART;
    if (bid >= SSTART) {
        int s = bid - SSTART;
        int r0 = (s * NN) / nslice, r1 = ((s + 1) * NN) / nslice;
        int c = t & 127, h6 = t >> 7;           // 6-way row split
        float m = 0.f, sq = 0.f;
        for (int r = r0 + h6; r < r1; r += 6) {
            float v = x[r * DD + c];
            m += v; sq += v * v;
        }
        s_sm[t] = m; s_ss[t] = sq;
        __syncthreads();
        if (t < 128) {
            float mm = 0.f;
            #pragma unroll
            for (int q = 0; q < 6; q++) mm += s_sm[t + 128 * q];
            g_partialM[s][t] = mm;
        }
        {
            double v = (double)s_ss[t];
            v = warp_red(v);
            if (lane == 0) s_red[w] = v;
            __syncthreads();
            if (w == 0) {
                double v2 = (lane < 24) ? s_red[lane] : 0.0;
                v2 = warp_red(v2);
                if (lane == 0) g_partialS[s] = v2;
            }
        }
    }

    // =========== final combine ===========================================
    if (t == 0) {
        __threadfence();
        int v = atomicAdd(&g_ticket, 1);
        s_isLast = (v == GRID - 1);
    }
    __syncthreads();
    if (s_isLast) {
        double mc = 0.0;
        if (t < 128) {
            for (int b = 0; b < nslice; b++) mc += (double)g_partialM[b][t];
            mc = mc * mc;
        }
        mc = warp_red(mc);
        if (lane == 0) s_red[w] = mc;
        __syncthreads();
        double msq = 0.0;
        if (w == 0) {
            double v = (lane < 24) ? s_red[lane] : 0.0;
            msq = warp_red(v);
        }
        __syncthreads();
        double v = 0.0;
        for (int i = t; i < nslice; i += THREADS) v += 2.0 * (double)NN * g_partialS[i];
        for (int i = t; i < ntasks; i += THREADS) v += g_tileRes[i];
        v = warp_red(v);
        if (lane == 0) s_red[w] = v;
        __syncthreads();
        if (w == 0) {
            double v2 = (lane < 24) ? s_red[lane] : 0.0;
            v2 = warp_red(v2);
            if (lane == 0) {
                double total = v2 - 2.0 * msq;
                out[0] = (float)(total / ((double)NN * (double)NN));
                g_ticket = 0;
                g_bar1 = 0u;
                g_bar2 = 0u;
            }
        }
    }
}

extern "C" void kernel_launch(void* const* d_in, const int* in_sizes, int n_in,
                              void* d_out, int out_size) {
    const float* x = (const float*)d_in[0];
    const int* y32 = (const int*)d_in[1];

    static int attr_set = 0;
    if (!attr_set) {
        cudaFuncSetAttribute(k_main, cudaFuncAttributeMaxDynamicSharedMemorySize, SMEM_DYN);
        attr_set = 1;
    }
    k_main<<<GRID, THREADS, SMEM_DYN>>>(x, y32, (float*)d_out);
}